// round 2
// baseline (speedup 1.0000x reference)
#include <cuda_runtime.h>
#include <cuda_bf16.h>
#include <cstdint>

// ============================================================================
// LSTM cell = one big split-bf16 GEMM (mma.sync path, compute_100-safe)
//   gates[4096,4096] = A[4096,2048] @ B^T
//   A = [x | h_prev] fp32 -> bf16 hi/lo split
//   B rows: n' = (j/8)*32 + gate*8 + (j%8)  (gate-block interleave)
//   3 GEMM terms folded into K loop: Ahi*Bhi + Ahi*Blo + Alo*Bhi
//   Fused LSTM epilogue straight from mma accumulators.
// ============================================================================

#define DEV __device__ __forceinline__

static constexpr int Bm = 4096;
static constexpr int Ed = 1024;
static constexpr int Hd = 1024;
static constexpr int Kd = 2048;
static constexpr int Nd = 4096;

static constexpr int BM = 128;
static constexpr int BN = 256;
static constexpr int BK = 64;                 // 64 bf16 = 128 B per row
static constexpr int NKIT = 3 * (Kd / BK);    // 96 (3 split terms x 32)
static constexpr int STAGES = 4;
static constexpr uint32_t A_STAGE_BYTES = BM * 128;          // 16384
static constexpr uint32_t B_STAGE_BYTES = BN * 128;          // 32768
static constexpr uint32_t STAGE_BYTES = A_STAGE_BYTES + B_STAGE_BYTES; // 49152
static constexpr uint32_t SMEM_DYN = STAGES * STAGE_BYTES;   // 196608

// --------------------------- scratch (global) -------------------------------
__device__ __nv_bfloat16 g_Ahi[(size_t)Bm * Kd];
__device__ __nv_bfloat16 g_Alo[(size_t)Bm * Kd];
__device__ __nv_bfloat16 g_Bhi[(size_t)Nd * Kd];
__device__ __nv_bfloat16 g_Blo[(size_t)Nd * Kd];

// ------------------------------ PTX helpers ---------------------------------
DEV uint32_t smem_u32(const void* p) {
    uint32_t a;
    asm("{ .reg .u64 t; cvta.to.shared.u64 t, %1; cvt.u32.u64 %0, t; }"
        : "=r"(a) : "l"(p));
    return a;
}
DEV void cp16(uint32_t dst, const void* src) {
    asm volatile("cp.async.cg.shared.global [%0], [%1], 16;"
                 :: "r"(dst), "l"(src) : "memory");
}
#define CP_COMMIT() asm volatile("cp.async.commit_group;" ::: "memory")
#define CP_WAIT(n)  asm volatile("cp.async.wait_group %0;" :: "n"(n) : "memory")

#define LDSM4(r, addr)                                                         \
    asm volatile("ldmatrix.sync.aligned.m8n8.x4.shared.b16 {%0,%1,%2,%3}, [%4];" \
                 : "=r"((r)[0]), "=r"((r)[1]), "=r"((r)[2]), "=r"((r)[3])      \
                 : "r"(addr))

#define MMA16816(d, a, b0, b1)                                                 \
    asm volatile("mma.sync.aligned.m16n8k16.row.col.f32.bf16.bf16.f32 "        \
                 "{%0,%1,%2,%3}, {%4,%5,%6,%7}, {%8,%9}, {%0,%1,%2,%3};"       \
                 : "+f"((d)[0]), "+f"((d)[1]), "+f"((d)[2]), "+f"((d)[3])      \
                 : "r"((a)[0]), "r"((a)[1]), "r"((a)[2]), "r"((a)[3]),         \
                   "r"(b0), "r"(b1))

#define SWZ(o) ((o) ^ (((o) >> 3) & 0x70))

// --------------------------- pack A (x | h_prev) ----------------------------
__global__ void pack_a_kernel(const float* __restrict__ x,
                              const float* __restrict__ hmem) {
    size_t idx = ((size_t)blockIdx.x * blockDim.x + threadIdx.x) * 4;
    int m = (int)(idx >> 11);
    int k = (int)(idx & 2047);
    const float* src = (k < Ed) ? (x + (size_t)m * Ed + k)
                                : (hmem + (size_t)m * Hd + (k - Ed));
    float4 v = *reinterpret_cast<const float4*>(src);
    __nv_bfloat16 h0 = __float2bfloat16(v.x);
    __nv_bfloat16 h1 = __float2bfloat16(v.y);
    __nv_bfloat16 h2 = __float2bfloat16(v.z);
    __nv_bfloat16 h3 = __float2bfloat16(v.w);
    __nv_bfloat16 l0 = __float2bfloat16(v.x - __bfloat162float(h0));
    __nv_bfloat16 l1 = __float2bfloat16(v.y - __bfloat162float(h1));
    __nv_bfloat16 l2 = __float2bfloat16(v.z - __bfloat162float(h2));
    __nv_bfloat16 l3 = __float2bfloat16(v.w - __bfloat162float(h3));
    *reinterpret_cast<__nv_bfloat162*>(g_Ahi + idx)     = __halves2bfloat162(h0, h1);
    *reinterpret_cast<__nv_bfloat162*>(g_Ahi + idx + 2) = __halves2bfloat162(h2, h3);
    *reinterpret_cast<__nv_bfloat162*>(g_Alo + idx)     = __halves2bfloat162(l0, l1);
    *reinterpret_cast<__nv_bfloat162*>(g_Alo + idx + 2) = __halves2bfloat162(l2, l3);
}

// ------------- pack B: transpose W/U -> [N',K] gate-block interleave --------
__global__ void pack_b_kernel(const float* __restrict__ Wi, const float* __restrict__ Ui,
                              const float* __restrict__ Wf, const float* __restrict__ Uf,
                              const float* __restrict__ Wo, const float* __restrict__ Uo,
                              const float* __restrict__ Wc, const float* __restrict__ Uc) {
    __shared__ float tile[32][33];
    int z = blockIdx.z;
    int gate = z >> 1, isU = z & 1;
    const float* src;
    switch (z) {
        case 0: src = Wi; break; case 1: src = Ui; break;
        case 2: src = Wf; break; case 3: src = Uf; break;
        case 4: src = Wo; break; case 5: src = Uo; break;
        case 6: src = Wc; break; default: src = Uc; break;
    }
    int tx = threadIdx.x, ty = threadIdx.y;      // 32 x 8
    int k0 = blockIdx.x * 32, j0 = blockIdx.y * 32;
    #pragma unroll
    for (int i = 0; i < 4; i++)
        tile[ty + 8 * i][tx] = src[(size_t)(k0 + ty + 8 * i) * Hd + (j0 + tx)];
    __syncthreads();
    #pragma unroll
    for (int i = 0; i < 4; i++) {
        int j = j0 + ty + 8 * i;
        float v = tile[tx][ty + 8 * i];
        size_t row = (size_t)((j >> 3) * 32 + gate * 8 + (j & 7));
        size_t col = (size_t)(isU * 1024 + k0 + tx);
        __nv_bfloat16 hv = __float2bfloat16(v);
        g_Bhi[row * Kd + col] = hv;
        g_Blo[row * Kd + col] = __float2bfloat16(v - __bfloat162float(hv));
    }
}

// ------------------------------- main GEMM ----------------------------------
__global__ __launch_bounds__(256, 1)
void lstm_gemm_kernel(const float* __restrict__ bi, const float* __restrict__ bff,
                      const float* __restrict__ bo, const float* __restrict__ bcc,
                      const float* __restrict__ hmem, float* __restrict__ out) {
    extern __shared__ char smem[];
    const uint32_t sb = smem_u32(smem);

    const int tid = threadIdx.x;
    const int lane = tid & 31;
    const int wid = tid >> 5;
    const int wm = wid >> 2;          // 0..1
    const int wn = wid & 3;           // 0..3
    const int m0 = blockIdx.x * BM;
    const int n0 = blockIdx.y * BN;

    float acc[4][8][4];
    #pragma unroll
    for (int f = 0; f < 4; f++)
        #pragma unroll
        for (int g = 0; g < 8; g++)
            #pragma unroll
            for (int r = 0; r < 4; r++) acc[f][g][r] = 0.0f;

    // ---- async stage loader: term t = kit/32 selects hi/lo operand pair ----
    auto load_stage = [&](int kit, int s) {
        const int term = kit >> 5;
        const int kb = (kit & 31) * BK;
        const __nv_bfloat16* Ag =
            (term == 2 ? g_Alo : g_Ahi) + (size_t)m0 * Kd + kb;
        const __nv_bfloat16* Bg =
            (term == 1 ? g_Blo : g_Bhi) + (size_t)n0 * Kd + kb;
        const uint32_t abase = sb + s * STAGE_BYTES;
        const uint32_t bbase = abase + A_STAGE_BYTES;
        #pragma unroll
        for (int i = 0; i < 4; i++) {              // A: 1024 x 16B chunks
            int c = tid + i * 256;
            int r = c >> 3, cc = c & 7;
            cp16(abase + SWZ((uint32_t)(r * 128 + cc * 16)),
                 Ag + (size_t)r * Kd + cc * 8);
        }
        #pragma unroll
        for (int i = 0; i < 8; i++) {              // B: 2048 x 16B chunks
            int c = tid + i * 256;
            int r = c >> 3, cc = c & 7;
            cp16(bbase + SWZ((uint32_t)(r * 128 + cc * 16)),
                 Bg + (size_t)r * Kd + cc * 8);
        }
    };

    // prologue: fill STAGES-1 stages
    #pragma unroll
    for (int s = 0; s < STAGES - 1; s++) {
        load_stage(s, s);
        CP_COMMIT();
    }

    for (int k = 0; k < NKIT; k++) {
        if (k + STAGES - 1 < NKIT) load_stage(k + STAGES - 1, (k + STAGES - 1) & 3);
        CP_COMMIT();
        CP_WAIT(STAGES - 1);
        __syncthreads();

        const uint32_t abase = sb + (k & 3) * STAGE_BYTES;
        const uint32_t bbase = abase + A_STAGE_BYTES;

        #pragma unroll
        for (int ks = 0; ks < 4; ks++) {
            const int bc = ks * 32 + ((lane >> 4) << 4);   // byte col for ldmatrix
            uint32_t af[4][4], bf4[4][4];
            #pragma unroll
            for (int f = 0; f < 4; f++) {
                int row = wm * 64 + f * 16 + (lane & 15);
                LDSM4(af[f], abase + SWZ((uint32_t)(row * 128 + bc)));
            }
            #pragma unroll
            for (int g2 = 0; g2 < 4; g2++) {
                int row = wn * 64 + g2 * 16 + (lane & 15);
                LDSM4(bf4[g2], bbase + SWZ((uint32_t)(row * 128 + bc)));
            }
            #pragma unroll
            for (int f = 0; f < 4; f++)
                #pragma unroll
                for (int g = 0; g < 8; g++) {
                    if (g & 1) MMA16816(acc[f][g], af[f], bf4[g >> 1][1], bf4[g >> 1][3]);
                    else       MMA16816(acc[f][g], af[f], bf4[g >> 1][0], bf4[g >> 1][2]);
                }
        }
        __syncthreads();
    }

    // ------------------------- fused LSTM epilogue --------------------------
    // warp n-slice = 64 n' = 2 blocks of 32; block = {gate0..3} x 8 j's
    // acc[f][jb*4+gate][c]: c0=(r,j) c1=(r,j+1) c2=(r+8,j) c3=(r+8,j+1)
    const float* cprev = hmem + (size_t)Bm * Hd;
    float* hout = out;
    float* cout = out + (size_t)Bm * Hd;

    #pragma unroll
    for (int jb = 0; jb < 2; jb++) {
        const int J = (blockIdx.y * 8 + wn * 2 + jb) * 8 + 2 * (lane & 3);
        const float bI0 = __ldg(bi + J),  bI1 = __ldg(bi + J + 1);
        const float bF0 = __ldg(bff + J), bF1 = __ldg(bff + J + 1);
        const float bO0 = __ldg(bo + J),  bO1 = __ldg(bo + J + 1);
        const float bC0 = __ldg(bcc + J), bC1 = __ldg(bcc + J + 1);
        #pragma unroll
        for (int f = 0; f < 4; f++) {
            const int r0 = m0 + wm * 64 + f * 16 + (lane >> 2);
            #pragma unroll
            for (int rr = 0; rr < 2; rr++) {
                const int m = r0 + rr * 8;
                #pragma unroll
                for (int jj = 0; jj < 2; jj++) {
                    const int ci = rr * 2 + jj;
                    float gi = acc[f][jb * 4 + 0][ci] + (jj ? bI1 : bI0);
                    float gf = acc[f][jb * 4 + 1][ci] + (jj ? bF1 : bF0);
                    float go = acc[f][jb * 4 + 2][ci] + (jj ? bO1 : bO0);
                    float gc = acc[f][jb * 4 + 3][ci] + (jj ? bC1 : bC0);
                    float iv = 1.0f / (1.0f + __expf(-gi));
                    float fv = 1.0f / (1.0f + __expf(-gf));
                    float ov = 1.0f / (1.0f + __expf(-go));
                    float cb = tanhf(gc);
                    float cv = fv * __ldg(cprev + (size_t)m * Hd + J + jj) + iv * cb;
                    float hv = ov * tanhf(cv);
                    hout[(size_t)m * Hd + J + jj] = hv;
                    cout[(size_t)m * Hd + J + jj] = cv;
                }
            }
        }
    }
}

// ------------------------------- launcher -----------------------------------
extern "C" void kernel_launch(void* const* d_in, const int* in_sizes, int n_in,
                              void* d_out, int out_size) {
    const float* x    = (const float*)d_in[0];
    const float* hmem = (const float*)d_in[1];
    const float* Wi = (const float*)d_in[2],  *Ui = (const float*)d_in[3];
    const float* bi = (const float*)d_in[4];
    const float* Wf = (const float*)d_in[5],  *Uf = (const float*)d_in[6];
    const float* bf = (const float*)d_in[7];
    const float* Wo = (const float*)d_in[8],  *Uo = (const float*)d_in[9];
    const float* bo = (const float*)d_in[10];
    const float* Wc = (const float*)d_in[11], *Uc = (const float*)d_in[12];
    const float* bc = (const float*)d_in[13];
    float* out = (float*)d_out;

    cudaFuncSetAttribute(lstm_gemm_kernel,
                         cudaFuncAttributeMaxDynamicSharedMemorySize, SMEM_DYN);

    pack_a_kernel<<<(Bm * Kd / 4 + 255) / 256, 256>>>(x, hmem);
    pack_b_kernel<<<dim3(32, 32, 8), dim3(32, 8)>>>(Wi, Ui, Wf, Uf, Wo, Uo, Wc, Uc);
    lstm_gemm_kernel<<<dim3(Bm / BM, Nd / BN), 256, SMEM_DYN>>>(bi, bf, bo, bc, hmem, out);
}

// round 3
// speedup vs baseline: 1.0140x; 1.0140x over previous
#include <cuda_runtime.h>
#include <cuda_bf16.h>
#include <cstdint>

// ============================================================================
// LSTM cell = one big split-bf16 GEMM (mma.sync path, compute_100-safe)
//   gates[4096,4096] = A[4096,2048] @ B^T
//   A = [x | h_prev] fp32 -> bf16 hi/lo split
//   B rows: n' = (j/8)*32 + gate*8 + (j%8)  (gate-block interleave)
//   FUSED 3-term K loop: per K-chunk load {Ahi,Alo,Bhi,Blo} once, issue
//   Ahi*Bhi + Ahi*Blo + Alo*Bhi reusing fragments. 32 iters, 2-stage ring.
//   Fused LSTM epilogue straight from mma accumulators.
// ============================================================================

#define DEV __device__ __forceinline__

static constexpr int Bm = 4096;
static constexpr int Ed = 1024;
static constexpr int Hd = 1024;
static constexpr int Kd = 2048;
static constexpr int Nd = 4096;

static constexpr int BM = 128;
static constexpr int BN = 256;
static constexpr int BK = 64;                  // 64 bf16 = 128 B per row
static constexpr int NKIT = Kd / BK;           // 32 fused iterations
static constexpr uint32_t STAGE_BYTES = 98304; // Ahi16K Alo16K Bhi32K Blo32K
static constexpr uint32_t SMEM_DYN = 2 * STAGE_BYTES; // 196608

// --------------------------- scratch (global) -------------------------------
__device__ __nv_bfloat16 g_Ahi[(size_t)Bm * Kd];
__device__ __nv_bfloat16 g_Alo[(size_t)Bm * Kd];
__device__ __nv_bfloat16 g_Bhi[(size_t)Nd * Kd];
__device__ __nv_bfloat16 g_Blo[(size_t)Nd * Kd];

// ------------------------------ PTX helpers ---------------------------------
DEV uint32_t smem_u32(const void* p) {
    uint32_t a;
    asm("{ .reg .u64 t; cvta.to.shared.u64 t, %1; cvt.u32.u64 %0, t; }"
        : "=r"(a) : "l"(p));
    return a;
}
DEV void cp16(uint32_t dst, const void* src) {
    asm volatile("cp.async.cg.shared.global [%0], [%1], 16;"
                 :: "r"(dst), "l"(src) : "memory");
}
#define CP_COMMIT() asm volatile("cp.async.commit_group;" ::: "memory")
#define CP_WAIT(n)  asm volatile("cp.async.wait_group %0;" :: "n"(n) : "memory")

#define LDSM4(r, addr)                                                         \
    asm volatile("ldmatrix.sync.aligned.m8n8.x4.shared.b16 {%0,%1,%2,%3}, [%4];" \
                 : "=r"((r)[0]), "=r"((r)[1]), "=r"((r)[2]), "=r"((r)[3])      \
                 : "r"(addr))

#define MMA16816(d, a, b0, b1)                                                 \
    asm volatile("mma.sync.aligned.m16n8k16.row.col.f32.bf16.bf16.f32 "        \
                 "{%0,%1,%2,%3}, {%4,%5,%6,%7}, {%8,%9}, {%0,%1,%2,%3};"       \
                 : "+f"((d)[0]), "+f"((d)[1]), "+f"((d)[2]), "+f"((d)[3])      \
                 : "r"((a)[0]), "r"((a)[1]), "r"((a)[2]), "r"((a)[3]),         \
                   "r"(b0), "r"(b1))

#define SWZ(o) ((o) ^ (((o) >> 3) & 0x70))

DEV float fast_sigmoid(float x) { return __frcp_rn(1.0f + __expf(-x)); }
DEV float fast_tanh(float x)    { return 1.0f - 2.0f * __frcp_rn(__expf(2.0f * x) + 1.0f); }

// --------------------------- pack A (x | h_prev) ----------------------------
__global__ void pack_a_kernel(const float* __restrict__ x,
                              const float* __restrict__ hmem) {
    size_t idx = ((size_t)blockIdx.x * blockDim.x + threadIdx.x) * 4;
    int m = (int)(idx >> 11);
    int k = (int)(idx & 2047);
    const float* src = (k < Ed) ? (x + (size_t)m * Ed + k)
                                : (hmem + (size_t)m * Hd + (k - Ed));
    float4 v = *reinterpret_cast<const float4*>(src);
    __nv_bfloat16 h0 = __float2bfloat16(v.x);
    __nv_bfloat16 h1 = __float2bfloat16(v.y);
    __nv_bfloat16 h2 = __float2bfloat16(v.z);
    __nv_bfloat16 h3 = __float2bfloat16(v.w);
    __nv_bfloat16 l0 = __float2bfloat16(v.x - __bfloat162float(h0));
    __nv_bfloat16 l1 = __float2bfloat16(v.y - __bfloat162float(h1));
    __nv_bfloat16 l2 = __float2bfloat16(v.z - __bfloat162float(h2));
    __nv_bfloat16 l3 = __float2bfloat16(v.w - __bfloat162float(h3));
    *reinterpret_cast<__nv_bfloat162*>(g_Ahi + idx)     = __halves2bfloat162(h0, h1);
    *reinterpret_cast<__nv_bfloat162*>(g_Ahi + idx + 2) = __halves2bfloat162(h2, h3);
    *reinterpret_cast<__nv_bfloat162*>(g_Alo + idx)     = __halves2bfloat162(l0, l1);
    *reinterpret_cast<__nv_bfloat162*>(g_Alo + idx + 2) = __halves2bfloat162(l2, l3);
}

// ------------- pack B: transpose W/U -> [N',K] gate-block interleave --------
__global__ void pack_b_kernel(const float* __restrict__ Wi, const float* __restrict__ Ui,
                              const float* __restrict__ Wf, const float* __restrict__ Uf,
                              const float* __restrict__ Wo, const float* __restrict__ Uo,
                              const float* __restrict__ Wc, const float* __restrict__ Uc) {
    __shared__ float tile[32][33];
    int z = blockIdx.z;
    int gate = z >> 1, isU = z & 1;
    const float* src;
    switch (z) {
        case 0: src = Wi; break; case 1: src = Ui; break;
        case 2: src = Wf; break; case 3: src = Uf; break;
        case 4: src = Wo; break; case 5: src = Uo; break;
        case 6: src = Wc; break; default: src = Uc; break;
    }
    int tx = threadIdx.x, ty = threadIdx.y;      // 32 x 8
    int k0 = blockIdx.x * 32, j0 = blockIdx.y * 32;
    #pragma unroll
    for (int i = 0; i < 4; i++)
        tile[ty + 8 * i][tx] = src[(size_t)(k0 + ty + 8 * i) * Hd + (j0 + tx)];
    __syncthreads();
    #pragma unroll
    for (int i = 0; i < 4; i++) {
        int j = j0 + ty + 8 * i;
        float v = tile[tx][ty + 8 * i];
        size_t row = (size_t)((j >> 3) * 32 + gate * 8 + (j & 7));
        size_t col = (size_t)(isU * 1024 + k0 + tx);
        __nv_bfloat16 hv = __float2bfloat16(v);
        g_Bhi[row * Kd + col] = hv;
        g_Blo[row * Kd + col] = __float2bfloat16(v - __bfloat162float(hv));
    }
}

// ------------------------------- main GEMM ----------------------------------
__global__ __launch_bounds__(256, 1)
void lstm_gemm_kernel(const float* __restrict__ bi, const float* __restrict__ bff,
                      const float* __restrict__ bo, const float* __restrict__ bcc,
                      const float* __restrict__ hmem, float* __restrict__ out) {
    extern __shared__ char smem[];
    const uint32_t sb = smem_u32(smem);

    const int tid = threadIdx.x;
    const int lane = tid & 31;
    const int wid = tid >> 5;
    const int wm = wid >> 2;          // 0..1
    const int wn = wid & 3;           // 0..3
    const int m0 = blockIdx.x * BM;
    const int n0 = blockIdx.y * BN;

    float acc[4][8][4];
    #pragma unroll
    for (int f = 0; f < 4; f++)
        #pragma unroll
        for (int g = 0; g < 8; g++)
            #pragma unroll
            for (int r = 0; r < 4; r++) acc[f][g][r] = 0.0f;

    // ---- async fused-stage loader: Ahi | Alo | Bhi | Blo per K-chunk -------
    auto load_stage = [&](int kit, int s) {
        const int kb = kit * BK;
        const __nv_bfloat16* gAh = g_Ahi + (size_t)m0 * Kd + kb;
        const __nv_bfloat16* gAl = g_Alo + (size_t)m0 * Kd + kb;
        const __nv_bfloat16* gBh = g_Bhi + (size_t)n0 * Kd + kb;
        const __nv_bfloat16* gBl = g_Blo + (size_t)n0 * Kd + kb;
        const uint32_t ah = sb + s * STAGE_BYTES;
        const uint32_t al = ah + 16384;
        const uint32_t bh = ah + 32768;
        const uint32_t bl = ah + 65536;
        #pragma unroll
        for (int i = 0; i < 4; i++) {              // A: 1024 x 16B chunks each
            int c = tid + i * 256;
            int r = c >> 3, cc = c & 7;
            uint32_t off = SWZ((uint32_t)(r * 128 + cc * 16));
            size_t go = (size_t)r * Kd + cc * 8;
            cp16(ah + off, gAh + go);
            cp16(al + off, gAl + go);
        }
        #pragma unroll
        for (int i = 0; i < 8; i++) {              // B: 2048 x 16B chunks each
            int c = tid + i * 256;
            int r = c >> 3, cc = c & 7;
            uint32_t off = SWZ((uint32_t)(r * 128 + cc * 16));
            size_t go = (size_t)r * Kd + cc * 8;
            cp16(bh + off, gBh + go);
            cp16(bl + off, gBl + go);
        }
    };

    // prologue: fill stage 0
    load_stage(0, 0);
    CP_COMMIT();

    for (int k = 0; k < NKIT; k++) {
        if (k + 1 < NKIT) load_stage(k + 1, (k + 1) & 1);
        CP_COMMIT();
        CP_WAIT(1);
        __syncthreads();

        const uint32_t ah = sb + (k & 1) * STAGE_BYTES;
        const uint32_t al = ah + 16384;
        const uint32_t bh = ah + 32768;
        const uint32_t bl = ah + 65536;

        #pragma unroll
        for (int ks = 0; ks < 4; ks++) {
            const int bc = ks * 32 + ((lane >> 4) << 4);   // byte col for ldsm
            uint32_t afh[4][4], afl[4][4], bfh[4][4], bfl[4][4];
            #pragma unroll
            for (int f = 0; f < 4; f++) {
                uint32_t ro = SWZ((uint32_t)((wm * 64 + f * 16 + (lane & 15)) * 128 + bc));
                LDSM4(afh[f], ah + ro);
                LDSM4(afl[f], al + ro);
            }
            #pragma unroll
            for (int g2 = 0; g2 < 4; g2++) {
                uint32_t ro = SWZ((uint32_t)((wn * 64 + g2 * 16 + (lane & 15)) * 128 + bc));
                LDSM4(bfh[g2], bh + ro);
                LDSM4(bfl[g2], bl + ro);
            }
            #pragma unroll
            for (int f = 0; f < 4; f++)
                #pragma unroll
                for (int g = 0; g < 8; g++) {
                    const int h = g >> 1;
                    if (g & 1) {
                        MMA16816(acc[f][g], afh[f], bfh[h][1], bfh[h][3]);
                        MMA16816(acc[f][g], afh[f], bfl[h][1], bfl[h][3]);
                        MMA16816(acc[f][g], afl[f], bfh[h][1], bfh[h][3]);
                    } else {
                        MMA16816(acc[f][g], afh[f], bfh[h][0], bfh[h][2]);
                        MMA16816(acc[f][g], afh[f], bfl[h][0], bfl[h][2]);
                        MMA16816(acc[f][g], afl[f], bfh[h][0], bfh[h][2]);
                    }
                }
        }
        __syncthreads();
    }

    // ------------------------- fused LSTM epilogue --------------------------
    // warp n-slice = 64 n' = 2 blocks of 32; block = {gate0..3} x 8 j's
    // acc[f][jb*4+gate][c]: c0=(r,j) c1=(r,j+1) c2=(r+8,j) c3=(r+8,j+1)
    const float* cprev = hmem + (size_t)Bm * Hd;
    float* hout = out;
    float* cout = out + (size_t)Bm * Hd;

    #pragma unroll
    for (int jb = 0; jb < 2; jb++) {
        const int J = (blockIdx.y * 8 + wn * 2 + jb) * 8 + 2 * (lane & 3);
        const float bI0 = __ldg(bi + J),  bI1 = __ldg(bi + J + 1);
        const float bF0 = __ldg(bff + J), bF1 = __ldg(bff + J + 1);
        const float bO0 = __ldg(bo + J),  bO1 = __ldg(bo + J + 1);
        const float bC0 = __ldg(bcc + J), bC1 = __ldg(bcc + J + 1);
        #pragma unroll
        for (int f = 0; f < 4; f++) {
            const int r0 = m0 + wm * 64 + f * 16 + (lane >> 2);
            #pragma unroll
            for (int rr = 0; rr < 2; rr++) {
                const int m = r0 + rr * 8;
                #pragma unroll
                for (int jj = 0; jj < 2; jj++) {
                    const int ci = rr * 2 + jj;
                    float gi = acc[f][jb * 4 + 0][ci] + (jj ? bI1 : bI0);
                    float gf = acc[f][jb * 4 + 1][ci] + (jj ? bF1 : bF0);
                    float go = acc[f][jb * 4 + 2][ci] + (jj ? bO1 : bO0);
                    float gc = acc[f][jb * 4 + 3][ci] + (jj ? bC1 : bC0);
                    float iv = fast_sigmoid(gi);
                    float fv = fast_sigmoid(gf);
                    float ov = fast_sigmoid(go);
                    float cb = fast_tanh(gc);
                    float cv = fv * __ldg(cprev + (size_t)m * Hd + J + jj) + iv * cb;
                    float hv = ov * fast_tanh(cv);
                    hout[(size_t)m * Hd + J + jj] = hv;
                    cout[(size_t)m * Hd + J + jj] = cv;
                }
            }
        }
    }
}

// ------------------------------- launcher -----------------------------------
extern "C" void kernel_launch(void* const* d_in, const int* in_sizes, int n_in,
                              void* d_out, int out_size) {
    const float* x    = (const float*)d_in[0];
    const float* hmem = (const float*)d_in[1];
    const float* Wi = (const float*)d_in[2],  *Ui = (const float*)d_in[3];
    const float* bi = (const float*)d_in[4];
    const float* Wf = (const float*)d_in[5],  *Uf = (const float*)d_in[6];
    const float* bf = (const float*)d_in[7];
    const float* Wo = (const float*)d_in[8],  *Uo = (const float*)d_in[9];
    const float* bo = (const float*)d_in[10];
    const float* Wc = (const float*)d_in[11], *Uc = (const float*)d_in[12];
    const float* bc = (const float*)d_in[13];
    float* out = (float*)d_out;

    cudaFuncSetAttribute(lstm_gemm_kernel,
                         cudaFuncAttributeMaxDynamicSharedMemorySize, SMEM_DYN);

    pack_a_kernel<<<(Bm * Kd / 4 + 255) / 256, 256>>>(x, hmem);
    pack_b_kernel<<<dim3(32, 32, 8), dim3(32, 8)>>>(Wi, Ui, Wf, Uf, Wo, Uo, Wc, Uc);
    lstm_gemm_kernel<<<dim3(Bm / BM, Nd / BN), 256, SMEM_DYN>>>(bi, bf, bo, bc, hmem, out);
}